// round 8
// baseline (speedup 1.0000x reference)
#include <cuda_runtime.h>
#include <cuda_fp16.h>

// Problem constants (fixed shapes from reference):
//   x:          [16,64,64,256] fp32  -> N_ROWS=65536 rows of D_DIM=256
//   dictionary: [256,1024]     fp32  -> D_DIM x K_CODES
// Output: q_st (16777216 fp32) followed by loss (1 fp32).
//
// CORRECTNESS-CRITICAL: the reference (XLA CPU fp32) computes
//   t2(k) = fl( fl(nf + c_k) - fl(2 * sim_k) ),  argmin_k first-index,
// with nf/c_k sequential fp32 square-sums over d and sim a sequential fp32
// FMA chain over d=0..255. Distances sit near 256 (grid ulp 3.05e-5).
// Strategy: fp16 HFMA2 screening (2 MACs/instr on the fma pipe) selects 48
// candidate codes per row; the EXACT fp32 reference arithmetic (validated
// bitwise in R6) is then replayed only for candidates. Do NOT alter the
// refine-path accumulation order or fuse/unfuse its ops.
#define D_DIM   256
#define K_CODES 1024
#define N_ROWS  65536

#define MTILE   128
#define NTILE   128
#define KCHUNK  32
#define ASTRIDE 260     // x-tile row stride (mult of 4 -> aligned float4)
#define THREADS 256
#define NCHUNK  64      // (1024/128 tiles) * (256/32 d-chunks)
#define NCAND   3       // top-3 approx candidates per thread per row
#define CPR     (16 * NCAND)   // candidates per row = 48
#define TOTC    (MTILE * CPR)  // 6144 candidates per CTA

// Scratch (no cudaMalloc): dictT fp32 (refine/gather), dict half (screen),
// code norms, loss accumulator.
__device__ float  g_dictT[K_CODES * D_DIM];
__device__ __half g_dictH[D_DIM * K_CODES];
__device__ float  g_c[K_CODES];
__device__ double g_loss;

// ---------------------------------------------------------------------------
// Kernel 1a: smem-tiled transpose dict[d][k] -> g_dictT[k][d] (coalesced both
// sides) for the refine chains and the epilogue gather.
// ---------------------------------------------------------------------------
__global__ void vq_transpose(const float* __restrict__ dict) {
    __shared__ float tile[32][33];
    const int kb = blockIdx.x * 32;
    const int db = blockIdx.y * 32;
    const int tx = threadIdx.x & 31;
    const int ty = threadIdx.x >> 5;
    #pragma unroll
    for (int r = ty; r < 32; r += 8)
        tile[r][tx] = dict[(size_t)(db + r) * K_CODES + kb + tx];
    __syncthreads();
    #pragma unroll
    for (int r = ty; r < 32; r += 8)
        g_dictT[(size_t)(kb + r) * D_DIM + db + tx] = tile[tx][r];
}

// ---------------------------------------------------------------------------
// Kernel 1b: half copy of dict in [d][k] layout for the HFMA2 screen.
// ---------------------------------------------------------------------------
__global__ void vq_tohalf(const float* __restrict__ dict) {
    int e = blockIdx.x * blockDim.x + threadIdx.x;
    if (e < D_DIM * K_CODES) g_dictH[e] = __float2half_rn(dict[e]);
}

// ---------------------------------------------------------------------------
// Kernel 1c: c_k = sum_d fl(d*d), SEQUENTIAL fp32 adds in d order (load-
// bearing for the argmin grid). Zero loss accumulator.
// ---------------------------------------------------------------------------
__global__ void vq_norms(const float* __restrict__ dict) {
    int k = blockIdx.x * blockDim.x + threadIdx.x;
    if (k == 0) g_loss = 0.0;
    if (k < K_CODES) {
        float c = 0.f;
        for (int d = 0; d < D_DIM; ++d) {
            float v = dict[(size_t)d * K_CODES + k];
            c = __fadd_rn(c, __fmul_rn(v, v));         // no FMA contraction
        }
        g_c[k] = c;
    }
}

// ---------------------------------------------------------------------------
// Kernel 2: per 128-row tile:
//  Phase 1 (screen): approx sims via __hfma2 (2 codes/instr), half partials
//    folded to fp32 every 16 d-steps; per-thread top-3 candidates per row.
//  Phase 2 (refine): exact fp32 reference arithmetic for 48 cand/row; winner
//    via smem atomicMin on (dist_bits<<32 | code) -> exact first-index ties.
//  Epilogue: gather q = 0.5*dictT[k*], write out, accumulate loss.
// Thread map (screen): j = t&15 owns 8 codes (4 half2 pairs), i = t>>4 owns
// rows {i, i+16, ..., i+112}. sBh double-buffered, register-staged prefetch.
// ---------------------------------------------------------------------------
__global__ __launch_bounds__(THREADS, 1)
void vq_main(const float* __restrict__ x,
             const float* __restrict__ dict,
             float* __restrict__ out) {
    extern __shared__ char smem[];
    float*  sA      = (float*)smem;                         // 128*260 fp32
    __half* sBh     = (__half*)(smem + 133120);             // 2 * 32*128 half
    int*    sCand   = (int*)(smem + 133120 + 16384);        // 6144 codes
    unsigned long long* rowBest =
        (unsigned long long*)(smem + 133120 + 16384 + 24576);   // 128 u64
    float*  sNf     = (float*)(smem + 174080 + 1024);       // 128 fp32
    int*    sIdx    = (int*)(smem + 175104 + 512);          // 128 int

    const int t = threadIdx.x;
    const int j = t & 15;
    const int i = t >> 4;
    const size_t row0 = (size_t)blockIdx.x * MTILE;

    // Load x tile (float4, coalesced) into SMEM
    {
        const float4* xv = (const float4*)(x + row0 * D_DIM);
        for (int e = t; e < MTILE * (D_DIM / 4); e += THREADS) {
            int r  = e >> 6;
            int c4 = e & 63;
            *(float4*)(sA + r * ASTRIDE + c4 * 4) = xv[r * 64 + c4];
        }
    }

    // Prefetch half-dict chunk 0 into registers (8 KB chunk, 32 B/thread)
    uint2 pf[4];
    {
        const uint2* dh = (const uint2*)g_dictH;   // 4 halfs per uint2
        #pragma unroll
        for (int q = 0; q < 4; ++q) {
            int e  = t + THREADS * q;              // 8-byte slot id
            int r  = e >> 5;                       // 32 slots per d-row
            int c8 = e & 31;
            pf[q] = dh[(size_t)r * (K_CODES / 4) + c8];
        }
    }
    __syncthreads();

    // Per-row nf = sum_d fl(x*x), sequential fp32 adds in d order.
    if (t < MTILE) {
        float s = 0.f;
        const float* rowp = sA + t * ASTRIDE;
        for (int d = 0; d < D_DIM; ++d)
            s = __fadd_rn(s, __fmul_rn(rowp[d], rowp[d]));
        sNf[t] = s;
        rowBest[t] = 0xFFFFFFFFFFFFFFFFull;
    }

    // Stage chunk 0 into buffer 0
    {
        uint2* dst = (uint2*)sBh;
        #pragma unroll
        for (int q = 0; q < 4; ++q) dst[t + THREADS * q] = pf[q];
    }
    __syncthreads();

    // Screening state
    float cv[8][NCAND];
    int   ci[8][NCAND];
    #pragma unroll
    for (int m = 0; m < 8; ++m)
        #pragma unroll
        for (int q = 0; q < NCAND; ++q) {
            cv[m][q] = __int_as_float(0x7f800000); ci[m][q] = 0;
        }

    float acc32[8][8];
    #pragma unroll
    for (int m = 0; m < 8; ++m)
        #pragma unroll
        for (int n = 0; n < 8; ++n) acc32[m][n] = 0.f;

    for (int c = 0; c < NCHUNK; ++c) {
        const int tt = c >> 3;
        const int kt = c & 7;
        const __half* sBuf = sBh + (c & 1) * (KCHUNK * NTILE);

        // Prefetch next chunk (LDG overlapped with compute)
        if (c + 1 < NCHUNK) {
            const int base_d = ((c + 1) & 7) * KCHUNK;
            const int base_c = ((c + 1) >> 3) * NTILE;
            const uint2* dh = (const uint2*)g_dictH;
            #pragma unroll
            for (int q = 0; q < 4; ++q) {
                int e  = t + THREADS * q;
                int r  = e >> 5;
                int c8 = e & 31;
                pf[q] = dh[(size_t)(base_d + r) * (K_CODES / 4) + (base_c / 4) + c8];
            }
        }

        // Approx HFMA2 GEMM: 2 halves of 16 d-steps, fp32 fold after each
        // (bounds fp16 accumulation error; screening only — order free).
        const int colbase = kt * KCHUNK;
        #pragma unroll
        for (int h = 0; h < 2; ++h) {
            __half2 aH[8][4];
            #pragma unroll
            for (int m = 0; m < 8; ++m)
                #pragma unroll
                for (int p = 0; p < 4; ++p) aH[m][p] = __float2half2_rn(0.f);

            #pragma unroll 8
            for (int kk = h * 16; kk < h * 16 + 16; ++kk) {
                __half2 a2[8];
                #pragma unroll
                for (int m = 0; m < 8; ++m)
                    a2[m] = __float2half2_rn(sA[(i + 16 * m) * ASTRIDE + colbase + kk]);
                const __half2* bh = (const __half2*)(sBuf + kk * NTILE) + j * 4;
                __half2 b2[4] = {bh[0], bh[1], bh[2], bh[3]};
                #pragma unroll
                for (int m = 0; m < 8; ++m)
                    #pragma unroll
                    for (int p = 0; p < 4; ++p)
                        aH[m][p] = __hfma2(a2[m], b2[p], aH[m][p]);
            }
            #pragma unroll
            for (int m = 0; m < 8; ++m)
                #pragma unroll
                for (int p = 0; p < 4; ++p) {
                    float2 s2 = __half22float2(aH[m][p]);
                    acc32[m][2 * p]     += s2.x;
                    acc32[m][2 * p + 1] += s2.y;
                }
        }

        // Publish prefetched chunk into the other buffer
        if (c + 1 < NCHUNK) {
            uint2* dst = (uint2*)(sBh + ((c + 1) & 1) * (KCHUNK * NTILE));
            #pragma unroll
            for (int q = 0; q < 4; ++q) dst[t + THREADS * q] = pf[q];
        }
        __syncthreads();

        if (kt == 7) {
            // Fold tile tt into per-row top-3 (ascending code order; strict
            // '<' keeps the earliest code ahead on approx ties).
            const int cbase = tt * NTILE + j * 8;
            #pragma unroll
            for (int n = 0; n < 8; ++n) {
                const float ck = g_c[cbase + n];
                const int code = cbase + n;
                #pragma unroll
                for (int m = 0; m < 8; ++m) {
                    float v = ck - 2.f * acc32[m][n];   // approx ranking value
                    if (v < cv[m][2]) {
                        if (v < cv[m][1]) {
                            cv[m][2] = cv[m][1]; ci[m][2] = ci[m][1];
                            if (v < cv[m][0]) {
                                cv[m][1] = cv[m][0]; ci[m][1] = ci[m][0];
                                cv[m][0] = v;        ci[m][0] = code;
                            } else { cv[m][1] = v;   ci[m][1] = code; }
                        } else     { cv[m][2] = v;   ci[m][2] = code; }
                    }
                }
            }
            #pragma unroll
            for (int m = 0; m < 8; ++m)
                #pragma unroll
                for (int n = 0; n < 8; ++n) acc32[m][n] = 0.f;
        }
    }

    // Publish candidates
    #pragma unroll
    for (int m = 0; m < 8; ++m) {
        int r = i + 16 * m;
        #pragma unroll
        for (int q = 0; q < NCAND; ++q)
            sCand[r * CPR + j * NCAND + q] = ci[m][q];
    }
    __syncthreads();

    // Refine: EXACT reference arithmetic for each candidate (4-way ILP).
    // sim chain: sequential fp32 fmaf over ascending d (bitwise = R6 chain);
    // then t1 = fl(nf + c_k), v = fl(t1 - fl(2*s)). Distances ~256 > 0, so
    // fp32 bits are order-preserving in the packed u64; low bits = code gives
    // first-index tie-breaking via atomicMin.
    for (int b = 0; b < TOTC / (THREADS * 4); ++b) {
        int rr[4], kk4[4];
        float s4[4] = {0.f, 0.f, 0.f, 0.f};
        #pragma unroll
        for (int u = 0; u < 4; ++u) {
            int id = t + THREADS * (4 * b + u);
            rr[u]  = id / CPR;
            kk4[u] = sCand[id];
        }
        for (int d = 0; d < D_DIM; d += 4) {
            #pragma unroll
            for (int u = 0; u < 4; ++u) {
                float4 dv = *(const float4*)(g_dictT + (size_t)kk4[u] * D_DIM + d);
                float4 xv = *(const float4*)(sA + rr[u] * ASTRIDE + d);
                float s = s4[u];
                s = fmaf(xv.x, dv.x, s);
                s = fmaf(xv.y, dv.y, s);
                s = fmaf(xv.z, dv.z, s);
                s = fmaf(xv.w, dv.w, s);
                s4[u] = s;
            }
        }
        #pragma unroll
        for (int u = 0; u < 4; ++u) {
            float t1 = __fadd_rn(sNf[rr[u]], g_c[kk4[u]]);
            float v  = __fsub_rn(t1, __fmul_rn(2.f, s4[u]));
            unsigned long long pk =
                ((unsigned long long)__float_as_uint(v) << 32) | (unsigned)kk4[u];
            atomicMin(&rowBest[rr[u]], pk);
        }
    }
    __syncthreads();

    if (t < MTILE) sIdx[t] = (int)(rowBest[t] & 0xFFFFFFFFull);
    __syncthreads();

    // Epilogue: gather q = 0.5*dictT[idx][d] (exact halving; coalesced),
    // write output, accumulate loss partial.
    float lsum = 0.f;
    for (int e = t; e < MTILE * D_DIM; e += THREADS) {
        int r = e >> 8;
        int d = e & 255;
        int idx = sIdx[r];
        float q  = 0.5f * g_dictT[(size_t)idx * D_DIM + d];
        float xv = sA[r * ASTRIDE + d];
        float df = xv - q;
        lsum = fmaf(df, df, lsum);
        out[(row0 + r) * D_DIM + d] = q;
    }

    #pragma unroll
    for (int o = 16; o > 0; o >>= 1)
        lsum += __shfl_xor_sync(0xffffffffu, lsum, o);
    float* sRed = (float*)sCand;          // reuse (candidates dead)
    __syncthreads();
    if ((t & 31) == 0) sRed[t >> 5] = lsum;
    __syncthreads();
    if (t == 0) {
        float s = 0.f;
        #pragma unroll
        for (int w = 0; w < THREADS / 32; ++w) s += sRed[w];
        atomicAdd(&g_loss, (double)s);
    }
}

// ---------------------------------------------------------------------------
// Kernel 3: loss = 1.25 * mean((x - q)^2)
// ---------------------------------------------------------------------------
__global__ void vq_finalize(float* __restrict__ out, int loss_idx) {
    out[loss_idx] = (float)(1.25 * g_loss * (1.0 / (double)(N_ROWS * D_DIM)));
}

static const int SMEM_BYTES = 176128;   // sA 133120 + sBh 16384 + sCand 24576
                                        // + rowBest 1024 + sNf 512 + sIdx 512

extern "C" void kernel_launch(void* const* d_in, const int* in_sizes, int n_in,
                              void* d_out, int out_size) {
    const float* x    = (const float*)d_in[0];
    const float* dict = (const float*)d_in[1];
    float* out = (float*)d_out;

    cudaFuncSetAttribute(vq_main, cudaFuncAttributeMaxDynamicSharedMemorySize,
                         SMEM_BYTES);

    vq_transpose<<<dim3(K_CODES / 32, D_DIM / 32), 256>>>(dict);
    vq_tohalf<<<(D_DIM * K_CODES + 255) / 256, 256>>>(dict);
    vq_norms<<<(K_CODES + 255) / 256, 256>>>(dict);
    vq_main<<<N_ROWS / MTILE, THREADS, SMEM_BYTES>>>(x, dict, out);
    vq_finalize<<<1, 1>>>(out, out_size - 1);
}